// round 16
// baseline (speedup 1.0000x reference)
#include <cuda_runtime.h>
#include <cuda_bf16.h>
#include <math.h>
#include <stdint.h>

#define B_SZ 8
#define T_SZ 2048
#define C_SZ 1024
#define H_SZ 64
#define WIN 64
#define NGLOB 64
#define NRAND 64
#define BT (B_SZ * T_SZ)

// Scratch: Q fp32; K,V pre-split bf16 hi/lo (bf16x2 words, 32 per token).
__device__ __align__(16) float    g_Q [BT * H_SZ];
__device__ __align__(16) uint32_t g_Kh[BT * 32];
__device__ __align__(16) uint32_t g_Kl[BT * 32];
__device__ __align__(16) uint32_t g_Vh[BT * 32];
__device__ __align__(16) uint32_t g_Vl[BT * 32];
// Pre-split W (Q|K|V rows), chunk-major pair-permuted bf16x2 words:
// g_wh[(c*192 + r)*8 + p]   (c = K-chunk 0..63)
__device__ __align__(16) uint32_t g_wh[192 * 512];
__device__ __align__(16) uint32_t g_wl[192 * 512];

__device__ __forceinline__ void mma_bf16(float* c, const uint32_t* a, const uint32_t* b) {
    asm volatile(
        "mma.sync.aligned.m16n8k16.row.col.f32.bf16.bf16.f32 "
        "{%0,%1,%2,%3}, {%4,%5,%6,%7}, {%8,%9}, {%0,%1,%2,%3};"
        : "+f"(c[0]), "+f"(c[1]), "+f"(c[2]), "+f"(c[3])
        : "r"(a[0]), "r"(a[1]), "r"(a[2]), "r"(a[3]), "r"(b[0]), "r"(b[1]));
}

__device__ __forceinline__ void ldmx2t(uint32_t& r0, uint32_t& r1, uint32_t addr) {
    asm volatile("ldmatrix.sync.aligned.m8n8.x2.trans.shared.b16 {%0,%1}, [%2];"
                 : "=r"(r0), "=r"(r1) : "r"(addr));
}

__device__ __forceinline__ void split2(float a, float b, uint32_t& hw, uint32_t& lw) {
    __nv_bfloat162 h2 = __floats2bfloat162_rn(a, b);
    hw = *(uint32_t*)&h2;
    float ra = a - __uint_as_float(hw << 16);
    float rb = b - __uint_as_float(hw & 0xFFFF0000u);
    __nv_bfloat162 l2 = __floats2bfloat162_rn(ra, rb);
    lw = *(uint32_t*)&l2;
}

__device__ __forceinline__ void cp16(void* smem_dst, const void* gsrc) {
    uint32_t sa = (uint32_t)__cvta_generic_to_shared(smem_dst);
    asm volatile("cp.async.cg.shared.global [%0], [%1], 16;" :: "r"(sa), "l"(gsrc));
}

__device__ __forceinline__ float bflo(uint32_t w) { return __uint_as_float(w << 16); }
__device__ __forceinline__ float bfhi(uint32_t w) { return __uint_as_float(w & 0xFFFF0000u); }

// ---------------------------------------------------------------------------
// Pre-split W only: 192 rows x 64 chunks, one thread per (row, chunk) group.
// Stores pair-permuted words so proj's fragment loads stay LDS.64.
// ---------------------------------------------------------------------------
__global__ __launch_bounds__(256) void presplit_w_kernel(
    const float* __restrict__ Wq, const float* __restrict__ Wk,
    const float* __restrict__ Wv)
{
    const int idx = blockIdx.x * 256 + threadIdx.x;
    if (idx >= 192 * 64) return;
    const int c = idx / 192, r = idx % 192;
    const float* src = ((r < 64)  ? Wq + (size_t)r * C_SZ
                      : (r < 128) ? Wk + (size_t)(r - 64) * C_SZ
                                  : Wv + (size_t)(r - 128) * C_SZ) + c * 16;
    float4 f[4];
#pragma unroll
    for (int i = 0; i < 4; i++) f[i] = ((const float4*)src)[i];
    const float* ff = (const float*)f;
    uint32_t hw[8], lw[8];
#pragma unroll
    for (int w = 0; w < 8; w++) {
        uint32_t h, l;
        split2(ff[2 * w], ff[2 * w + 1], h, l);
        const int p = 2 * (w & 3) + (w >> 2);   // pair-permute
        hw[p] = h; lw[p] = l;
    }
    const size_t goff = (size_t)idx * 8;        // (c*192 + r) * 8
    ((uint4*)(g_wh + goff))[0] = make_uint4(hw[0], hw[1], hw[2], hw[3]);
    ((uint4*)(g_wh + goff))[1] = make_uint4(hw[4], hw[5], hw[6], hw[7]);
    ((uint4*)(g_wl + goff))[0] = make_uint4(lw[0], lw[1], lw[2], lw[3]);
    ((uint4*)(g_wl + goff))[1] = make_uint4(lw[4], lw[5], lw[6], lw[7]);
}

// ---------------------------------------------------------------------------
// FUSED projection GEMM (Q,K,V): round-14 structure (ping-pong smem, one
// barrier/chunk, split-major MMA, verified epilogue). W-fill replaced by
// 3 cp.async 16B copies/thread from the presplit table (issued right after
// the barrier, waited before the next publish barrier -> overlaps MMA).
// x-fill (2 slots, LDG+split+STS) unchanged.
// ---------------------------------------------------------------------------
#define KC 16
#define PADK 12
#define NCHUNK (C_SZ / KC)

__global__ __launch_bounds__(256, 2) void proj_tc_kernel(const float* __restrict__ x)
{
    __shared__ __align__(16) uint32_t sm_h[2][256][PADK];
    __shared__ __align__(16) uint32_t sm_l[2][256][PADK];

    const int m0 = blockIdx.x * 64;
    const int tid = threadIdx.x, warp = tid >> 5, lane = tid & 31;
    const int grp = lane >> 2, tig = lane & 3;
    const int mh = warp & 1, nq = warp >> 1;

    // x fill: 2 slots (64 rows x 8 words)
    const float* xsrc[2];
    int xrp[2];
#pragma unroll
    for (int it = 0; it < 2; it++) {
        const int i = it * 256 + tid;          // 0..511
        const int row = i >> 3, w = i & 7;
        xsrc[it] = x + (size_t)(m0 + row) * C_SZ + w * 2;
        xrp[it] = row * PADK + 2 * (w & 3) + (w >> 2);
    }

    // W fill: 3 cp16 slots (768 uint4 per chunk: hi 384 + lo 384)
    const uint32_t* wsrc[3];
    int wdst[3];
    bool wlo[3];
#pragma unroll
    for (int s = 0; s < 3; s++) {
        const int g = s * 256 + tid;           // 0..767
        const bool fl = (g >= 384);
        const int rem = g - (fl ? 384 : 0);    // 0..383
        const int row = rem >> 1, half = rem & 1;
        wsrc[s] = (fl ? g_wl : g_wh) + row * 8 + half * 4;   // + c*1536
        wdst[s] = (64 + row) * PADK + half * 4;              // within one buffer
        wlo[s] = fl;
    }

#define WFILL(C, BUF) do {                                                    \
        _Pragma("unroll")                                                     \
        for (int _s = 0; _s < 3; _s++) {                                      \
            uint32_t* _base = wlo[_s] ? &sm_l[BUF][0][0] : &sm_h[BUF][0][0];  \
            cp16(_base + wdst[_s], wsrc[_s] + (size_t)(C) * 1536);            \
        }                                                                     \
        asm volatile("cp.async.commit_group;");                               \
    } while (0)

    float acc[2][6][4];
#pragma unroll
    for (int mt = 0; mt < 2; mt++)
#pragma unroll
        for (int i = 0; i < 6; i++)
#pragma unroll
            for (int j = 0; j < 4; j++) acc[mt][i][j] = 0.f;

    // prologue: buffer 0 = chunk 0
    WFILL(0, 0);
    float2 pf[2];
#pragma unroll
    for (int it = 0; it < 2; it++) pf[it] = *(const float2*)xsrc[it];
#pragma unroll
    for (int it = 0; it < 2; it++) {
        uint32_t hu, lu;
        split2(pf[it].x, pf[it].y, hu, lu);
        (&sm_h[0][0][0])[xrp[it]] = hu;
        (&sm_l[0][0][0])[xrp[it]] = lu;
    }
    asm volatile("cp.async.wait_group 0;");

    for (int c = 0; c < NCHUNK; c++) {
        __syncthreads();                       // publish buf[c&1]; free other
        const int cur = c & 1;
        const bool more = (c + 1 < NCHUNK);

        if (more) {
            WFILL(c + 1, cur ^ 1);             // async W fill under MMA
#pragma unroll
            for (int it = 0; it < 2; it++)     // x loads for next chunk
                pf[it] = *(const float2*)(xsrc[it] + (c + 1) * KC);
        }

        // a-fragments
        uint32_t ah[2][4], al[2][4];
#pragma unroll
        for (int mt = 0; mt < 2; mt++) {
            const int mrow = mh * 32 + mt * 16 + grp;
            uint2 q0 = *(const uint2*)&sm_h[cur][mrow][tig * 2];
            uint2 q1 = *(const uint2*)&sm_h[cur][mrow + 8][tig * 2];
            ah[mt][0] = q0.x; ah[mt][2] = q0.y; ah[mt][1] = q1.x; ah[mt][3] = q1.y;
            uint2 s0 = *(const uint2*)&sm_l[cur][mrow][tig * 2];
            uint2 s1 = *(const uint2*)&sm_l[cur][mrow + 8][tig * 2];
            al[mt][0] = s0.x; al[mt][2] = s0.y; al[mt][1] = s1.x; al[mt][3] = s1.y;
        }
        // b-fragments preloaded, then split-major MMA issue
        uint32_t bh[6][2], bl[6][2];
#pragma unroll
        for (int i = 0; i < 6; i++) {
            const int wrow = 64 + (nq * 6 + i) * 8 + grp;
            uint2 bh2 = *(const uint2*)&sm_h[cur][wrow][tig * 2];
            uint2 bl2 = *(const uint2*)&sm_l[cur][wrow][tig * 2];
            bh[i][0] = bh2.x; bh[i][1] = bh2.y;
            bl[i][0] = bl2.x; bl[i][1] = bl2.y;
        }
#pragma unroll
        for (int i = 0; i < 6; i++)
#pragma unroll
            for (int mt = 0; mt < 2; mt++)
                mma_bf16(acc[mt][i], al[mt], bh[i]);
#pragma unroll
        for (int i = 0; i < 6; i++)
#pragma unroll
            for (int mt = 0; mt < 2; mt++)
                mma_bf16(acc[mt][i], ah[mt], bl[i]);
#pragma unroll
        for (int i = 0; i < 6; i++)
#pragma unroll
            for (int mt = 0; mt < 2; mt++)
                mma_bf16(acc[mt][i], ah[mt], bh[i]);

        if (more) {
            const int nxt = cur ^ 1;
#pragma unroll
            for (int it = 0; it < 2; it++) {
                uint32_t hu, lu;
                split2(pf[it].x, pf[it].y, hu, lu);
                (&sm_h[nxt][0][0])[xrp[it]] = hu;
                (&sm_l[nxt][0][0])[xrp[it]] = lu;
            }
            asm volatile("cp.async.wait_group 0;");   // W copies landed
        }
    }

    // epilogue: Q fp32; K,V split bf16 hi/lo (verified mapping)
#pragma unroll
    for (int mt = 0; mt < 2; mt++) {
        const int mwr = m0 + mh * 32 + mt * 16 + grp;
#pragma unroll
        for (int i = 0; i < 6; i++) {
            const int ntg = nq * 6 + i;
            const float a0 = acc[mt][i][0], a1 = acc[mt][i][1];
            const float a2 = acc[mt][i][2], a3 = acc[mt][i][3];
            if (ntg < 8) {
                const int col = ntg * 8 + tig * 2;
                *(float2*)&g_Q[(size_t)mwr * H_SZ + col]       = make_float2(a0, a1);
                *(float2*)&g_Q[(size_t)(mwr + 8) * H_SZ + col] = make_float2(a2, a3);
            } else {
                uint32_t* dh = (ntg < 16) ? g_Kh : g_Vh;
                uint32_t* dl = (ntg < 16) ? g_Kl : g_Vl;
                const int word = (ntg & 7) * 4 + tig;
                uint32_t hu, lu;
                split2(a0, a1, hu, lu);
                dh[(size_t)mwr * 32 + word] = hu;
                dl[(size_t)mwr * 32 + word] = lu;
                split2(a2, a3, hu, lu);
                dh[(size_t)(mwr + 8) * 32 + word] = hu;
                dl[(size_t)(mwr + 8) * 32 + word] = lu;
            }
        }
    }
}

// ---------------------------------------------------------------------------
// Hybrid sparse BigBird attention (ROUND-14 VERBATIM — passed at 69 us).
// ---------------------------------------------------------------------------
#define QR 16
#define NDENSE 192
#define KST 36
#define SHIFT 12.0f
#define TILE_W (64 * KST)
#define POOL_W (2 * 16 * KST)
#define SMEM_ATTN ((4 * TILE_W + POOL_W + 3 * 1024) * 4 + (NDENSE + QR * 64) * 2)

__global__ __launch_bounds__(256, 3) void attn16_kernel(
    const int* __restrict__ random_cols, float* __restrict__ out)
{
    extern __shared__ __align__(16) uint32_t dyn[];
    uint32_t* KH = dyn;
    uint32_t* KL = KH + TILE_W;
    uint32_t* VH = KL + TILE_W;
    uint32_t* VL = VH + TILE_W;
    uint32_t* POOL = VL + TILE_W;
    float*    QS  = (float*)(POOL + POOL_W);
    float*    OR_ = QS + 1024;
    uint32_t* RBIT = (uint32_t*)(OR_ + 1024);
    uint16_t* cols  = (uint16_t*)(RBIT + 1024);
    uint16_t* rlist = cols + NDENSE;

    __shared__ float lred[8][16];
    __shared__ float l_r[16];
    __shared__ int rcnt[16];

    uint32_t (*ph)[KST] = (uint32_t(*)[KST])POOL;
    uint32_t (*pl)[KST] = (uint32_t(*)[KST])(POOL + 16 * KST);

    const int blk = blockIdx.x;
    const int b   = blk >> 7;
    const int r0  = (blk & 127) * QR;
    const int r3  = r0 + QR - 1;
    const int tid = threadIdx.x, wid = tid >> 5, lane = tid & 31;
    const int grp = lane >> 2, tig = lane & 3;
    const int l8 = lane & 7, g8 = lane >> 3;
    const size_t bbase = (size_t)b * T_SZ;

    const int lo0 = max(0, r0 - (WIN - 1));
    const int gn  = min(NGLOB, r3 + 1);
    const int l0u = max(64, lo0);
    const int ln  = max(0, r3 - l0u + 1);
    const int nd  = gn + ln;
    const int ndt = (nd + 63) >> 6;

    for (int i = tid; i < QR * 64; i += 256) {
        QS[i] = g_Q[(bbase + r0 + (i >> 6)) * H_SZ + (i & 63)] * 0.125f;
        OR_[i] = 0.f;
        RBIT[i] = 0;
    }
    if (tid < 16) { rcnt[tid] = 0; l_r[tid] = 0.f; }
    __syncthreads();

    uint32_t aqh[4][4], aql[4][4];
#pragma unroll
    for (int ks = 0; ks < 4; ks++) {
        const float* qA = QS + grp * 64 + ks * 16 + 2 * tig;
        const float* qB = QS + (grp + 8) * 64 + ks * 16 + 2 * tig;
        split2(qA[0], qA[1], aqh[ks][0], aql[ks][0]);
        split2(qB[0], qB[1], aqh[ks][1], aql[ks][1]);
        split2(qA[8], qA[9], aqh[ks][2], aql[ks][2]);
        split2(qB[8], qB[9], aqh[ks][3], aql[ks][3]);
    }

    if (tid < gn) cols[tid] = (uint16_t)tid;
    if (tid >= 64 && tid < 64 + ln) cols[gn + tid - 64] = (uint16_t)(l0u + tid - 64);
    for (int i = tid; i < QR * NRAND; i += 256) {
        const int row = i >> 6;
        const int v = random_cols[(r0 + row) * NRAND + (i & 63)];
        const uint32_t bit = 1u << (v & 31);
        const uint32_t old = atomicOr(&RBIT[row * 64 + (v >> 5)], bit);
        if (v >= 64 && v < l0u && !(old & bit))
            rlist[row * 64 + atomicAdd(&rcnt[row], 1)] = (uint16_t)v;
    }
    __syncthreads();

    const int glc = tid >> 3;
    const int gch = (tid & 7) << 2;
#define GATHER(T) do {                                                        \
        const int _t0 = (T) << 6;                                             \
        _Pragma("unroll")                                                     \
        for (int _e = 0; _e < 2; _e++) {                                      \
            const int _lc = glc + _e * 32;                                    \
            const int _idx = _t0 + _lc;                                       \
            const int _cg = (_idx < nd) ? (int)cols[_idx] : 0;                \
            const size_t _gb = (bbase + _cg) * 32 + gch;                      \
            const int _so = _lc * KST + gch;                                  \
            cp16(&KH[_so], &g_Kh[_gb]);                                       \
            cp16(&KL[_so], &g_Kl[_gb]);                                       \
            cp16(&VH[_so], &g_Vh[_gb]);                                       \
            cp16(&VL[_so], &g_Vl[_gb]);                                       \
        }                                                                     \
        asm volatile("cp.async.commit_group;");                               \
        asm volatile("cp.async.wait_group 0;");                               \
    } while (0)

    GATHER(0);

    float oc0[4] = {0.f,0.f,0.f,0.f};
    float oc1[4] = {0.f,0.f,0.f,0.f};
    float oc2[4] = {0.f,0.f,0.f,0.f};
    float lA = 0.f, lB = 0.f;

    for (int t = 0; t < ndt; t++) {
        __syncthreads();

        float s0[4] = {0.f,0.f,0.f,0.f};
        float s1[4] = {0.f,0.f,0.f,0.f};
        float s2[4] = {0.f,0.f,0.f,0.f};
        const int kr = (wid << 3) + grp;
#pragma unroll
        for (int ks = 0; ks < 4; ks++) {
            const int o = kr * KST + (ks << 3) + tig;
            uint32_t bh[2] = { KH[o], KH[o + 4] };
            uint32_t bl[2] = { KL[o], KL[o + 4] };
            mma_bf16(s0, aql[ks], bh);
            mma_bf16(s1, aqh[ks], bl);
            mma_bf16(s2, aqh[ks], bh);
        }
        float sc[4];
#pragma unroll
        for (int j = 0; j < 4; j++) sc[j] = s0[j] + s1[j] + s2[j];

        const int iA = (t << 6) + (wid << 3) + (tig << 1);
        const int cA = (iA < nd) ? (int)cols[iA] : -1;
        const int cB = (iA + 1 < nd) ? (int)cols[iA + 1] : -1;
        const int rA = r0 + grp, rB = rA + 8;
#define OKM(r, c, rl) ((c) >= 0 && (c) <= (r) && ((c) > (r) - WIN || (c) < NGLOB || \
                       ((RBIT[(rl) * 64 + ((c) >> 5)] >> ((c) & 31)) & 1u)))
        const float p00 = OKM(rA, cA, grp)     ? __expf(sc[0] - SHIFT) : 0.f;
        const float p01 = OKM(rA, cB, grp)     ? __expf(sc[1] - SHIFT) : 0.f;
        const float p10 = OKM(rB, cA, grp + 8) ? __expf(sc[2] - SHIFT) : 0.f;
        const float p11 = OKM(rB, cB, grp + 8) ? __expf(sc[3] - SHIFT) : 0.f;
#undef OKM
        lA += p00 + p01;
        lB += p10 + p11;

        {
            const int w = (wid << 2) + tig;
            const int pp = ((w >> 3) << 3) + ((w & 3) << 1) + ((w >> 2) & 1);
            uint32_t hw, lw;
            split2(p00, p01, hw, lw);
            ph[grp][pp] = hw; pl[grp][pp] = lw;
            split2(p10, p11, hw, lw);
            ph[grp + 8][pp] = hw; pl[grp + 8][pp] = lw;
        }
        __syncthreads();

#pragma unroll
        for (int ks = 0; ks < 4; ks++) {
            uint32_t pah[4], pal[4];
            uint2 t0 = *(const uint2*)&ph[grp][(ks << 3) + (tig << 1)];
            uint2 t1 = *(const uint2*)&ph[grp + 8][(ks << 3) + (tig << 1)];
            pah[0] = t0.x; pah[2] = t0.y; pah[1] = t1.x; pah[3] = t1.y;
            uint2 t2 = *(const uint2*)&pl[grp][(ks << 3) + (tig << 1)];
            uint2 t3 = *(const uint2*)&pl[grp + 8][(ks << 3) + (tig << 1)];
            pal[0] = t2.x; pal[2] = t2.y; pal[1] = t3.x; pal[3] = t3.y;

            const int vo = ((ks << 4) + (lane & 15)) * KST + (wid << 2);
            uint32_t bvh[2], bvl[2];
            ldmx2t(bvh[0], bvh[1], (uint32_t)__cvta_generic_to_shared(&VH[vo]));
            ldmx2t(bvl[0], bvl[1], (uint32_t)__cvta_generic_to_shared(&VL[vo]));
            mma_bf16(oc0, pal, bvh);
            mma_bf16(oc1, pah, bvl);
            mma_bf16(oc2, pah, bvh);
        }
        __syncthreads();

        if (t + 1 < ndt) GATHER(t + 1);
    }

    float oc[4];
#pragma unroll
    for (int j = 0; j < 4; j++) oc[j] = oc0[j] + oc1[j] + oc2[j];

#pragma unroll
    for (int half = 0; half < 2; half++) {
        const int rr = wid + half * 8;
        const int cnt = rcnt[rr];
        float qreg[8];
#pragma unroll
        for (int d = 0; d < 8; d++) qreg[d] = QS[rr * 64 + 8 * l8 + d];
        float o8[8] = {0.f,0.f,0.f,0.f,0.f,0.f,0.f,0.f};
        float lp = 0.f;

        for (int j0 = 0; j0 < cnt; j0 += 4) {
            const int j = j0 + g8;
            const bool act = (j < cnt);
            const int c = (int)rlist[rr * 64 + (act ? j : 0)];
            const size_t gb = (bbase + c) * 32 + 4 * l8;
            const uint4 khw = *(const uint4*)&g_Kh[gb];
            const uint4 klw = *(const uint4*)&g_Kl[gb];
            const uint4 vhw = *(const uint4*)&g_Vh[gb];
            const uint4 vlw = *(const uint4*)&g_Vl[gb];

            float p = qreg[0] * (bflo(khw.x) + bflo(klw.x))
                    + qreg[1] * (bfhi(khw.x) + bfhi(klw.x))
                    + qreg[2] * (bflo(khw.y) + bflo(klw.y))
                    + qreg[3] * (bfhi(khw.y) + bfhi(klw.y))
                    + qreg[4] * (bflo(khw.z) + bflo(klw.z))
                    + qreg[5] * (bfhi(khw.z) + bfhi(klw.z))
                    + qreg[6] * (bflo(khw.w) + bflo(klw.w))
                    + qreg[7] * (bfhi(khw.w) + bfhi(klw.w));
            p += __shfl_xor_sync(0xffffffffu, p, 1);
            p += __shfl_xor_sync(0xffffffffu, p, 2);
            p += __shfl_xor_sync(0xffffffffu, p, 4);
            const float wgt = act ? __expf(p - SHIFT) : 0.f;
            if (l8 == 0) lp += wgt;
            o8[0] += wgt * (bflo(vhw.x) + bflo(vlw.x));
            o8[1] += wgt * (bfhi(vhw.x) + bfhi(vlw.x));
            o8[2] += wgt * (bflo(vhw.y) + bflo(vlw.y));
            o8[3] += wgt * (bfhi(vhw.y) + bfhi(vlw.y));
            o8[4] += wgt * (bflo(vhw.z) + bflo(vlw.z));
            o8[5] += wgt * (bfhi(vhw.z) + bfhi(vlw.z));
            o8[6] += wgt * (bflo(vhw.w) + bflo(vlw.w));
            o8[7] += wgt * (bfhi(vhw.w) + bfhi(vlw.w));
        }
#pragma unroll
        for (int d = 0; d < 8; d++) {
            o8[d] += __shfl_xor_sync(0xffffffffu, o8[d], 8);
            o8[d] += __shfl_xor_sync(0xffffffffu, o8[d], 16);
        }
        lp += __shfl_xor_sync(0xffffffffu, lp, 8);
        lp += __shfl_xor_sync(0xffffffffu, lp, 16);
        if (g8 == 0) {
#pragma unroll
            for (int d = 0; d < 8; d++) OR_[rr * 64 + 8 * l8 + d] = o8[d];
            if (l8 == 0) l_r[rr] = lp;
        }
    }

    lA += __shfl_xor_sync(0xffffffffu, lA, 1);
    lA += __shfl_xor_sync(0xffffffffu, lA, 2);
    lB += __shfl_xor_sync(0xffffffffu, lB, 1);
    lB += __shfl_xor_sync(0xffffffffu, lB, 2);
    if (tig == 0) { lred[wid][grp] = lA; lred[wid][grp + 8] = lB; }
    __syncthreads();

    float sA = l_r[grp], sB = l_r[grp + 8];
#pragma unroll
    for (int w2 = 0; w2 < 8; w2++) { sA += lred[w2][grp]; sB += lred[w2][grp + 8]; }

    const int dim = (wid << 3) + (tig << 1);
    const float iA2 = 1.f / sA, iB2 = 1.f / sB;
    *(float2*)&out[(bbase + r0 + grp) * H_SZ + dim] =
        make_float2((oc[0] + OR_[grp * 64 + dim]) * iA2,
                    (oc[1] + OR_[grp * 64 + dim + 1]) * iA2);
    *(float2*)&out[(bbase + r0 + grp + 8) * H_SZ + dim] =
        make_float2((oc[2] + OR_[(grp + 8) * 64 + dim]) * iB2,
                    (oc[3] + OR_[(grp + 8) * 64 + dim + 1]) * iB2);
}

// ---------------------------------------------------------------------------
// kernel_launch — inputs per metadata order: x, random_cols, Wk, Wq, Wv
// ---------------------------------------------------------------------------
extern "C" void kernel_launch(void* const* d_in, const int* in_sizes, int n_in,
                              void* d_out, int out_size)
{
    const float* x           = (const float*)d_in[0];
    const int*   random_cols = (const int*)  d_in[1];
    const float* Wk          = (const float*)d_in[2];
    const float* Wq          = (const float*)d_in[3];
    const float* Wv          = (const float*)d_in[4];
    float* out = (float*)d_out;

    static bool attr_set = false;
    if (!attr_set) {
        cudaFuncSetAttribute(attn16_kernel,
                             cudaFuncAttributeMaxDynamicSharedMemorySize,
                             SMEM_ATTN);
        attr_set = true;
    }

    presplit_w_kernel<<<(192 * 64 + 255) / 256, 256>>>(Wq, Wk, Wv);
    proj_tc_kernel<<<BT / 64, 256>>>(x);
    attn16_kernel<<<BT / QR, 256, SMEM_ATTN>>>(random_cols, out);
}